// round 14
// baseline (speedup 1.0000x reference)
#include <cuda_runtime.h>
#include <stdint.h>

#define PI_F 3.14159265358979323846f

#define LDIM 512
#define ADIM 181
#define PDIM 1024
#define BDIM 2

#define RP    516                 // pairs per row (float2): p in [0,512] used, padded to 516
#define ROWB  (RP * 8)            // row bytes = 4128 (divisible by 16)
#define CH    13                  // angles per staging buffer (x2 batch rows each)
#define BUFB  (CH * 2 * ROWB)     // 107328 bytes per buffer (rows interleaved b0,b1)
#define MAGIC 8388608.0f          // 2^23 ; MAGIC-0.5f = 8388607.5 IS representable (ulp 0.5)

#define BPT   1024                // k_bp threads per block (32 x 32); 1 block/SM

typedef unsigned long long ull;

// ---------------- device scratch (no allocation allowed) ----------------
__device__ float  g_F[PDIM];                    // frequency filter (ramp * shifted hann)
__device__ float  g_hr[PDIM];                   // real(ifft(F))  -- time-domain taps
__device__ float2 g_trig[ADIM];                 // (cos th, sin th), th = angle + pi/2
__device__ float2 g_pairs[BDIM * ADIM][RP];     // pair[p] = (c_p, d_p): value = c_p + u'*d_p

// ---------------- asm helpers ----------------
__device__ __forceinline__ uint32_t smem_u32(const void* p) {
    uint32_t a;
    asm("{ .reg .u64 t; cvta.to.shared.u64 t, %1; cvt.u32.u64 %0, t; }" : "=r"(a) : "l"(p));
    return a;
}
__device__ __forceinline__ void cpa16(uint32_t saddr, const void* g) {
    asm volatile("cp.async.cg.shared.global [%0], [%1], 16;" :: "r"(saddr), "l"(g));
}
__device__ __forceinline__ void cpa_commit() {
    asm volatile("cp.async.commit_group;" ::: "memory");
}
__device__ __forceinline__ void cpa_wait0() {
    asm volatile("cp.async.wait_group 0;" ::: "memory");
}
__device__ __forceinline__ float2 lds64(uint32_t addr) {
    float2 g;
    asm volatile("ld.shared.v2.f32 {%0,%1}, [%2];" : "=f"(g.x), "=f"(g.y) : "r"(addr));
    return g;
}
__device__ __forceinline__ float2 lds64_b1(uint32_t addr) {   // batch-1 row: +ROWB immediate
    float2 g;
    asm volatile("ld.shared.v2.f32 {%0,%1}, [%2+4128];" : "=f"(g.x), "=f"(g.y) : "r"(addr));
    return g;
}
__device__ __forceinline__ ull pack2(float lo, float hi) {
    ull d;
    asm("mov.b64 %0, {%1, %2};" : "=l"(d) : "f"(lo), "f"(hi));
    return d;
}
__device__ __forceinline__ ull fma2(ull a, ull b, ull c) {
    ull d;
    asm("fma.rn.f32x2 %0, %1, %2, %3;" : "=l"(d) : "l"(a), "l"(b), "l"(c));
    return d;
}
__device__ __forceinline__ ull add2(ull a, ull b) {
    ull d;
    asm("add.rn.f32x2 %0, %1, %2;" : "=l"(d) : "l"(a), "l"(b));
    return d;
}
__device__ __forceinline__ float lo2(ull d) { return __uint_as_float((unsigned)d); }
__device__ __forceinline__ float hi2(ull d) { return __uint_as_float((unsigned)(d >> 32)); }

// ---------------- F[k] = ramp[k] * fftshift(hanning(P))[k]  (+ trig, + zero d_out) ----------------
__global__ void k_ramp(const float* __restrict__ angles, int A,
                       float4* __restrict__ outz, int out_n4) {
    __shared__ float sred[4];
    int k = blockIdx.x;
    int t = threadIdx.x; // 128 threads

    // zero the output (replaces cudaMemsetAsync): 1024 blocks x 128 threads x 1 float4
    int zi = k * 128 + t;
    if (zi < out_n4) outz[zi] = make_float4(0.f, 0.f, 0.f, 0.f);

    float sum = 0.f;
    for (int j = t; j < 256; j += 128) {
        int m = 2 * j + 1;
        float fm = -1.0f / (PI_F * PI_F * (float)m * (float)m);
        int ph = (k * m) & (PDIM - 1);
        sum = fmaf(fm, cospif((float)ph * (1.0f / 512.0f)), sum);
    }
    #pragma unroll
    for (int o = 16; o; o >>= 1) sum += __shfl_down_sync(0xffffffffu, sum, o);
    if ((t & 31) == 0) sred[t >> 5] = sum;
    __syncthreads();
    if (t == 0) {
        float total = sred[0] + sred[1] + sred[2] + sred[3];
        float ramp = 0.5f + 4.0f * total;
        int i = (k + PDIM / 2) & (PDIM - 1);                       // fftshift index
        float w = 0.5f - 0.5f * cospif(2.0f * (float)i / 1023.0f); // np.hanning(1024)
        g_F[k] = ramp * w;
    }
    if (blockIdx.x == 0) {
        for (int a = t; a < A && a < ADIM; a += 128) {
            float th = angles[a] + PI_F * 0.5f;
            float s, c;
            sincosf(th, &s, &c);
            g_trig[a] = make_float2(c, s);
        }
    }
}

// ---------------- hr[n] = (1/P) * sum_k F[k] cos(2*pi*k*n/P) ----------------
__global__ void k_hr(void) {
    __shared__ float sred[8];
    int n = blockIdx.x;
    int t = threadIdx.x; // 256 threads
    float sum = 0.f;
    for (int k = t; k < PDIM; k += 256) {
        int ph = (k * n) & (PDIM - 1);
        sum = fmaf(g_F[k], cospif((float)ph * (1.0f / 512.0f)), sum);
    }
    #pragma unroll
    for (int o = 16; o; o >>= 1) sum += __shfl_down_sync(0xffffffffu, sum, o);
    if ((t & 31) == 0) sred[t >> 5] = sum;
    __syncthreads();
    if (t == 0) {
        float total = 0.f;
        #pragma unroll
        for (int w = 0; w < 8; w++) total += sred[w];
        g_hr[n] = total * (1.0f / (float)PDIM);
    }
}

// ---------------- filtering + affine-pair construction ----------------
// y[n] = sum_m x[m] hr[(n-m) mod 1024];  pair[p] = (c_p, d_p):
//   d_p = y[p]-y[p-1],  c_p = y[p-1] - p*d_p,  y[-1]=y[512]=0.
// In pair coords u' = t + 256.5 (cell p = floor(u')), interp value = c_p + u' * d_p.
__global__ void __launch_bounds__(128) k_filter(const float* __restrict__ sino) {
    __shared__ float xs[LDIM];
    __shared__ float hsx[1536];
    __shared__ float ysb[520];   // ysb[i] = y[i-1]; ysb[0]=0
    int row = blockIdx.x;
    int t = threadIdx.x; // 128
    const float4* x4 = (const float4*)(sino + row * LDIM);
    ((float4*)xs)[t] = x4[t];
    #pragma unroll
    for (int q = t; q < 384; q += 128)
        ((float4*)hsx)[q] = ((const float4*)g_hr)[q & 255];
    if (t == 0) ysb[0] = 0.f;
    __syncthreads();

    const int qb = 1024 + 4 * t;
    float4 Av = *(const float4*)(hsx + qb - 4);
    float4 Bv = *(const float4*)(hsx + qb);
    float acc0 = 0.f, acc1 = 0.f, acc2 = 0.f, acc3 = 0.f;

    #pragma unroll 4
    for (int m0 = 0; m0 < LDIM; m0 += 4) {
        float4 xv = *(const float4*)(xs + m0);
        float w0 = Av.x, w1 = Av.y, w2 = Av.z, w3 = Av.w;
        float w4 = Bv.x, w5 = Bv.y, w6 = Bv.z, w7 = Bv.w;
        acc0 = fmaf(xv.x, w4, fmaf(xv.y, w3, fmaf(xv.z, w2, fmaf(xv.w, w1, acc0))));
        acc1 = fmaf(xv.x, w5, fmaf(xv.y, w4, fmaf(xv.z, w3, fmaf(xv.w, w2, acc1))));
        acc2 = fmaf(xv.x, w6, fmaf(xv.y, w5, fmaf(xv.z, w4, fmaf(xv.w, w3, acc2))));
        acc3 = fmaf(xv.x, w7, fmaf(xv.y, w6, fmaf(xv.z, w5, fmaf(xv.w, w4, acc3))));
        Bv = Av;
        Av = *(const float4*)(hsx + qb - m0 - 8);
    }
    // y[4t..4t+3] -> ysb[4t+1 .. 4t+4]
    ysb[4 * t + 1] = acc0;
    ysb[4 * t + 2] = acc1;
    ysb[4 * t + 3] = acc2;
    ysb[4 * t + 4] = acc3;
    __syncthreads();

    float e0 = ysb[4 * t];       // y[4t-1]
    float pf = (float)(4 * t);   // pair index p for first of the 4
    float d0 = acc0 - e0;    float c0 = fmaf(-pf,          d0, e0);
    float d1 = acc1 - acc0;  float c1 = fmaf(-(pf + 1.0f), d1, acc0);
    float d2 = acc2 - acc1;  float c2 = fmaf(-(pf + 2.0f), d2, acc1);
    float d3 = acc3 - acc2;  float c3 = fmaf(-(pf + 3.0f), d3, acc2);
    float4* prow = (float4*)(&g_pairs[row][0]);
    prow[2 * t]     = make_float4(c0, d0, c1, d1);
    prow[2 * t + 1] = make_float4(c2, d2, c3, d3);
    if (t == 127)    // pair 512: d = -y[511], c = y[511] - 512*(-y[511]) = 513*y[511]
        g_pairs[row][512] = make_float2(513.0f * acc3, -acc3);
}

// ---------------- backprojection (batch-merged, angle-split, single-sync pipeline) ----------------
// block = (32,32) = 1024 threads, 1 block/SM; tile = 32 (j) x 64 (i, 2 per thread),
// BOTH batches per block (batch-1 row at +ROWB immediate -> shared index math).
// blockIdx.z = angle half. Partial sums atomicAdd'ed into pre-zeroed output
// (<=2 adds per pixel, commutative -> bitwise deterministic, per-batch order unchanged).
__global__ void __launch_bounds__(BPT, 1) k_bp(
    float* __restrict__ out, const int* __restrict__ circ, int A, int B)
{
    extern __shared__ float sm[];
    float2* strig = (float2*)(sm + 2 * (BUFB / 4));

    const int tx = threadIdx.x, ty = threadIdx.y;
    const int tid = ty * 32 + tx;
    const int h  = blockIdx.z;
    const int j  = blockIdx.x * 32 + tx;
    const int i0 = blockIdx.y * 64 + ty;     // 2 px: i0, i0+32
    const int circle = circ[0];

    // whole-block early exit: tile entirely outside the circle (output pre-zeroed)
    if (circle) {
        int j0 = (int)blockIdx.x * 32, ib = (int)blockIdx.y * 64;
        int djlo = j0 - 256, djhi = j0 + 31 - 256;
        int djm = djlo > 0 ? djlo : (djhi < 0 ? -djhi : 0);
        int dilo = ib - 256, dihi = ib + 63 - 256;
        int dim_ = dilo > 0 ? dilo : (dihi < 0 ? -dihi : 0);
        if (djm * djm + dim_ * dim_ > 65536) return;
    }

    const int Ah = (A + 1) / 2;
    const int aStart = h * Ah;
    const int aEnd   = min(A, aStart + Ah);

    for (int a = tid + aStart; a < aEnd; a += BPT) strig[a] = g_trig[a];

    const int dj = j - LDIM / 2;
    const float djf = (float)dj;
    float accA0[2], accB0[2], accA1[2], accB1[2], fdi[2];
    unsigned maskbits = 0;
    #pragma unroll
    for (int k = 0; k < 2; k++) {
        accA0[k] = accB0[k] = accA1[k] = accB1[k] = 0.f;
        int di = i0 + 32 * k - LDIM / 2;
        bool outside = (di * di + dj * dj) > (LDIM / 2) * (LDIM / 2);
        if (outside) maskbits |= (1u << k);
        fdi[k] = (circle && outside) ? 0.0f : (float)di;
    }
    const ull fdi2 = pack2(fdi[0], fdi[1]);
    const ull mh2  = pack2(MAGIC - 0.5f, MAGIC - 0.5f);  // 8388607.5, representable

    const uint32_t sb = smem_u32(sm);
    const int b1row = (B > 1) ? A : 0;       // batch-1 source offset (dup b0 if B==1)
    const int nch = (aEnd - aStart + CH - 1) / CH;

    // stage chunk c: slot s = 2*(a-a0) + batch, rows interleaved so b1 = b0 + ROWB
    auto stage = [&](int cidx) {
        int a0 = aStart + cidx * CH;
        int ch = min(CH, aEnd - a0);
        uint32_t base = sb + (uint32_t)(cidx & 1) * BUFB;
        for (int s = 0; s < 2 * ch; s++) {
            int a = a0 + (s >> 1);
            int rowsrc = (s & 1) ? (b1row + a) : a;
            const char* gsrc = (const char*)(&g_pairs[rowsrc][0]);
            uint32_t dst = base + (uint32_t)s * ROWB;
            for (int c = tid; c < ROWB / 16; c += BPT)
                cpa16(dst + (uint32_t)c * 16, gsrc + c * 16);
        }
        cpa_commit();
    };

    stage(0);

    for (int cidx = 0; cidx < nch; cidx++) {
        int a0 = aStart + cidx * CH;
        int ch = min(CH, aEnd - a0);

        cpa_wait0();             // this thread's groups (incl. chunk cidx) complete
        __syncthreads();         // all threads' data visible; all done computing cidx-1
        if (cidx + 1 < nch) stage(cidx + 1);   // buffer (cidx+1)&1 provably free

        uint32_t bb = sb + (uint32_t)(cidx & 1) * BUFB;
        if (circle) {
            for (int r = 0; r < ch; r++) {
                float2 cs = strig[a0 + r];
                float base = fmaf(djf, cs.y, 256.5f);          // u' = t + 256.5 in [0.5,512.5]
                ull csx2  = pack2(cs.x, cs.x);
                ull base2 = pack2(base, base);
                // batch0 row at slot 2r; addr = bits(m)*8 + off; batch1 at +ROWB imm
                uint32_t off = bb + (uint32_t)(2 * r) * ROWB - 0x58000000u;
                ull u2 = fma2(fdi2, csx2, base2);
                ull m2 = add2(u2, mh2);                        // bits = 0x4B000000 + floor(u')
                uint32_t ad0 = (uint32_t)m2 * 8u + off;
                uint32_t ad1 = (uint32_t)(m2 >> 32) * 8u + off;
                float2 g00 = lds64(ad0);
                float2 g01 = lds64(ad1);
                float2 g10 = lds64_b1(ad0);
                float2 g11 = lds64_b1(ad1);
                accA0[0] += g00.x;  accB0[0] = fmaf(lo2(u2), g00.y, accB0[0]);
                accA0[1] += g01.x;  accB0[1] = fmaf(hi2(u2), g01.y, accB0[1]);
                accA1[0] += g10.x;  accB1[0] = fmaf(lo2(u2), g10.y, accB1[0]);
                accA1[1] += g11.x;  accB1[1] = fmaf(hi2(u2), g11.y, accB1[1]);
            }
        } else {
            for (int r = 0; r < ch; r++) {
                float2 cs = strig[a0 + r];
                float base = fmaf(djf, cs.y, 256.5f);          // u' in pair coords
                uint32_t rowa = bb + (uint32_t)(2 * r) * ROWB;
                #pragma unroll
                for (int k = 0; k < 2; k++) {
                    float u = fmaf(fdi[k], cs.x, base);
                    int p = __float2int_rd(u);
                    float f = u - __int2float_rn(p);
                    int pc = min(max(p, 0), 512);
                    uint32_t ad = rowa + (uint32_t)pc * 8u;
                    float2 g0 = lds64(ad);
                    float2 g1 = lds64_b1(ad);
                    // endpoints of cell pc from affine coeffs: y0 = c + p*d, y1 = y0 + d
                    float y00 = fmaf((float)pc, g0.y, g0.x);
                    float y01 = y00 + g0.y;
                    float y10 = fmaf((float)pc, g1.y, g1.x);
                    float y11 = y10 + g1.y;
                    float w0 = (p >= 1 && p <= 512) ? (1.0f - f) : 0.0f;
                    float w1 = (p >= 0 && p <= 511) ? f : 0.0f;
                    accA0[k] = fmaf(w0, y00, fmaf(w1, y01, accA0[k]));
                    accA1[k] = fmaf(w0, y10, fmaf(w1, y11, accA1[k]));
                }
            }
        }
    }

    #pragma unroll
    for (int k = 0; k < 2; k++) {
        int ii = i0 + 32 * k;
        if (circle && ((maskbits >> k) & 1u)) continue;     // out pre-zeroed
        atomicAdd(&out[(size_t)ii * LDIM + j], accA0[k] + accB0[k]);
        if (B > 1)
            atomicAdd(&out[((size_t)LDIM + ii) * LDIM + j], accA1[k] + accB1[k]);
    }
}

// ---------------- launch ----------------
extern "C" void kernel_launch(void* const* d_in, const int* in_sizes, int n_in,
                              void* d_out, int out_size) {
    int si = 0, ai = 1, ci = 2;
    for (int i = 0; i < n_in; i++)
        if (in_sizes[i] > in_sizes[si]) si = i;
    for (int i = 0; i < n_in; i++) {
        if (i == si) continue;
        if (in_sizes[i] == 1) ci = i; else ai = i;
    }
    const float* sino   = (const float*)d_in[si];
    const float* angles = (const float*)d_in[ai];
    const int*   circ   = (const int*)d_in[ci];

    int A = in_sizes[ai];
    if (A > ADIM) A = ADIM;
    int BL = in_sizes[si] / A;
    int B  = BL / LDIM;
    if (B < 1) B = 1;
    if (B > BDIM) B = BDIM;
    int nrows = B * A;

    k_ramp<<<PDIM, 128>>>(angles, A, (float4*)d_out, out_size / 4);
    k_hr<<<PDIM, 256>>>();
    k_filter<<<nrows, 128>>>(sino);

    size_t smem = (size_t)(2 * BUFB) + (size_t)ADIM * sizeof(float2) + 16;
    cudaFuncSetAttribute(k_bp, cudaFuncAttributeMaxDynamicSharedMemorySize, (int)smem);
    dim3 grid(LDIM / 32, LDIM / 64, 2);   // z = angle half; batches merged in-block
    dim3 blk(32, 32);
    k_bp<<<grid, blk, smem>>>((float*)d_out, circ, A, B);
}

// round 15
// speedup vs baseline: 1.1018x; 1.1018x over previous
#include <cuda_runtime.h>
#include <cuda_fp16.h>
#include <stdint.h>

#define PI_F 3.14159265358979323846f

#define LDIM 512
#define ADIM 181
#define PDIM 1024
#define BDIM 2

#define RP    516                 // pairs per row (half2): p in [0,512] used, padded to 516
#define ROWB  (RP * 4)            // row bytes = 2064 (divisible by 16)
#define CH    23                  // angle rows per staging buffer (double-buffered)
#define BUFB  (CH * ROWB)         // 47472 bytes per buffer
#define MAGIC 8388608.0f          // 2^23 ; MAGIC-0.5f = 8388607.5 IS representable (ulp 0.5)

#define BPT   512                 // k_bp threads per block (32 x 16)

typedef unsigned long long ull;

// ---------------- device scratch (no allocation allowed) ----------------
__device__ float  g_F[PDIM];                    // frequency filter (ramp * shifted hann)
__device__ float  g_hr[PDIM];                   // real(ifft(F))  -- time-domain taps
__device__ float2 g_trig[ADIM];                 // (cos th, sin th), th = angle + pi/2
// pair[p] = half2(y[p-1], y[p]-y[p-1]);  16B-aligned base for cp.async
__device__ __align__(16) __half2 g_pairsh[BDIM * ADIM][RP];

// ---------------- asm helpers ----------------
__device__ __forceinline__ uint32_t smem_u32(const void* p) {
    uint32_t a;
    asm("{ .reg .u64 t; cvta.to.shared.u64 t, %1; cvt.u32.u64 %0, t; }" : "=r"(a) : "l"(p));
    return a;
}
__device__ __forceinline__ void cpa16(uint32_t saddr, const void* g) {
    asm volatile("cp.async.cg.shared.global [%0], [%1], 16;" :: "r"(saddr), "l"(g));
}
__device__ __forceinline__ void cpa_commit() {
    asm volatile("cp.async.commit_group;" ::: "memory");
}
__device__ __forceinline__ void cpa_wait0() {
    asm volatile("cp.async.wait_group 0;" ::: "memory");
}
__device__ __forceinline__ uint32_t lds32(uint32_t addr) {
    uint32_t v;
    asm volatile("ld.shared.b32 %0, [%1];" : "=r"(v) : "r"(addr));
    return v;
}
__device__ __forceinline__ ull pack2(float lo, float hi) {
    ull d;
    asm("mov.b64 %0, {%1, %2};" : "=l"(d) : "f"(lo), "f"(hi));
    return d;
}
__device__ __forceinline__ ull fma2(ull a, ull b, ull c) {
    ull d;
    asm("fma.rn.f32x2 %0, %1, %2, %3;" : "=l"(d) : "l"(a), "l"(b), "l"(c));
    return d;
}
__device__ __forceinline__ ull add2(ull a, ull b) {
    ull d;
    asm("add.rn.f32x2 %0, %1, %2;" : "=l"(d) : "l"(a), "l"(b));
    return d;
}
__device__ __forceinline__ float lo2(ull d) { return __uint_as_float((unsigned)d); }
__device__ __forceinline__ float hi2(ull d) { return __uint_as_float((unsigned)(d >> 32)); }
__device__ __forceinline__ float2 h2f2(uint32_t v) {
    __half2 h = *reinterpret_cast<__half2*>(&v);
    return __half22float2(h);
}

// ---------------- F[k] = ramp[k] * fftshift(hanning(P))[k]  (+ trig, + zero d_out) ----------------
__global__ void k_ramp(const float* __restrict__ angles, int A,
                       float4* __restrict__ outz, int out_n4) {
    __shared__ float sred[4];
    int k = blockIdx.x;
    int t = threadIdx.x; // 128 threads

    // zero the output: 1024 blocks x 128 threads x 1 float4
    int zi = k * 128 + t;
    if (zi < out_n4) outz[zi] = make_float4(0.f, 0.f, 0.f, 0.f);

    float sum = 0.f;
    for (int j = t; j < 256; j += 128) {
        int m = 2 * j + 1;
        float fm = -1.0f / (PI_F * PI_F * (float)m * (float)m);
        int ph = (k * m) & (PDIM - 1);
        sum = fmaf(fm, cospif((float)ph * (1.0f / 512.0f)), sum);
    }
    #pragma unroll
    for (int o = 16; o; o >>= 1) sum += __shfl_down_sync(0xffffffffu, sum, o);
    if ((t & 31) == 0) sred[t >> 5] = sum;
    __syncthreads();
    if (t == 0) {
        float total = sred[0] + sred[1] + sred[2] + sred[3];
        float ramp = 0.5f + 4.0f * total;
        int i = (k + PDIM / 2) & (PDIM - 1);                       // fftshift index
        float w = 0.5f - 0.5f * cospif(2.0f * (float)i / 1023.0f); // np.hanning(1024)
        g_F[k] = ramp * w;
    }
    if (blockIdx.x == 0) {
        for (int a = t; a < A && a < ADIM; a += 128) {
            float th = angles[a] + PI_F * 0.5f;
            float s, c;
            sincosf(th, &s, &c);
            g_trig[a] = make_float2(c, s);
        }
    }
}

// ---------------- hr[n] = (1/P) * sum_k F[k] cos(2*pi*k*n/P) ----------------
__global__ void k_hr(void) {
    __shared__ float sred[8];
    int n = blockIdx.x;
    int t = threadIdx.x; // 256 threads
    float sum = 0.f;
    for (int k = t; k < PDIM; k += 256) {
        int ph = (k * n) & (PDIM - 1);
        sum = fmaf(g_F[k], cospif((float)ph * (1.0f / 512.0f)), sum);
    }
    #pragma unroll
    for (int o = 16; o; o >>= 1) sum += __shfl_down_sync(0xffffffffu, sum, o);
    if ((t & 31) == 0) sred[t >> 5] = sum;
    __syncthreads();
    if (t == 0) {
        float total = 0.f;
        #pragma unroll
        for (int w = 0; w < 8; w++) total += sred[w];
        g_hr[n] = total * (1.0f / (float)PDIM);
    }
}

// ---------------- filtering + fp16 delta-pair construction ----------------
// y[n] = sum_m x[m] hr[(n-m) mod 1024];  pair[p] = half2(y[p-1], y[p]-y[p-1]); y[-1]=y[512]=0.
// In pair coords u' = t + 256.5 (cell p = floor(u')), value = y0 + frac(u') * delta.
__global__ void __launch_bounds__(128) k_filter(const float* __restrict__ sino) {
    __shared__ float xs[LDIM];
    __shared__ float hsx[1536];
    __shared__ float ysb[520];   // ysb[i] = y[i-1]; ysb[0]=0
    int row = blockIdx.x;
    int t = threadIdx.x; // 128
    const float4* x4 = (const float4*)(sino + row * LDIM);
    ((float4*)xs)[t] = x4[t];
    #pragma unroll
    for (int q = t; q < 384; q += 128)
        ((float4*)hsx)[q] = ((const float4*)g_hr)[q & 255];
    if (t == 0) ysb[0] = 0.f;
    __syncthreads();

    const int qb = 1024 + 4 * t;
    float4 Av = *(const float4*)(hsx + qb - 4);
    float4 Bv = *(const float4*)(hsx + qb);
    float acc0 = 0.f, acc1 = 0.f, acc2 = 0.f, acc3 = 0.f;

    #pragma unroll 4
    for (int m0 = 0; m0 < LDIM; m0 += 4) {
        float4 xv = *(const float4*)(xs + m0);
        float w0 = Av.x, w1 = Av.y, w2 = Av.z, w3 = Av.w;
        float w4 = Bv.x, w5 = Bv.y, w6 = Bv.z, w7 = Bv.w;
        acc0 = fmaf(xv.x, w4, fmaf(xv.y, w3, fmaf(xv.z, w2, fmaf(xv.w, w1, acc0))));
        acc1 = fmaf(xv.x, w5, fmaf(xv.y, w4, fmaf(xv.z, w3, fmaf(xv.w, w2, acc1))));
        acc2 = fmaf(xv.x, w6, fmaf(xv.y, w5, fmaf(xv.z, w4, fmaf(xv.w, w3, acc2))));
        acc3 = fmaf(xv.x, w7, fmaf(xv.y, w6, fmaf(xv.z, w5, fmaf(xv.w, w4, acc3))));
        Bv = Av;
        Av = *(const float4*)(hsx + qb - m0 - 8);
    }
    // y[4t..4t+3] -> ysb[4t+1 .. 4t+4]
    ysb[4 * t + 1] = acc0;
    ysb[4 * t + 2] = acc1;
    ysb[4 * t + 3] = acc2;
    ysb[4 * t + 4] = acc3;
    __syncthreads();

    float e0 = ysb[4 * t];       // y[4t-1]
    __half2 h0 = __floats2half2_rn(e0,   acc0 - e0);
    __half2 h1 = __floats2half2_rn(acc0, acc1 - acc0);
    __half2 h2 = __floats2half2_rn(acc1, acc2 - acc1);
    __half2 h3 = __floats2half2_rn(acc2, acc3 - acc2);
    uint4 w;
    w.x = *(uint32_t*)&h0;  w.y = *(uint32_t*)&h1;
    w.z = *(uint32_t*)&h2;  w.w = *(uint32_t*)&h3;
    *(uint4*)(&g_pairsh[row][4 * t]) = w;     // byte offset 16*t, aligned
    if (t == 127)    // pair 512 = (y[511], 0 - y[511])
        g_pairsh[row][512] = __floats2half2_rn(acc3, -acc3);
}

// ---------------- backprojection (fp16 pairs, angle-split, single-sync pipeline) ----------------
// block = (32,16) = 512 threads, 2 blocks/SM; tile = 32 (j) x 64 (i, 4 per thread).
// blockIdx.z = (batch, angle-half). LDS.32 half2 per sample (crossbar halved),
// magic floor for address + frac (R6-proven constants). atomicAdd into pre-zeroed
// output (<=2 adds per pixel, commutative -> deterministic).
__global__ void __launch_bounds__(BPT, 2) k_bp(
    float* __restrict__ out, const int* __restrict__ circ, int A, int B)
{
    extern __shared__ float sm[];
    float2* strig = (float2*)(sm + 2 * (BUFB / 4));

    const int tx = threadIdx.x, ty = threadIdx.y;
    const int tid = ty * 32 + tx;
    const int b  = blockIdx.z >> 1;
    const int h  = blockIdx.z & 1;
    const int j  = blockIdx.x * 32 + tx;
    const int i0 = blockIdx.y * 64 + ty;
    const int circle = circ[0];

    // whole-block early exit: tile entirely outside the circle (output pre-zeroed)
    if (circle) {
        int j0 = (int)blockIdx.x * 32, ib = (int)blockIdx.y * 64;
        int djlo = j0 - 256, djhi = j0 + 31 - 256;
        int djm = djlo > 0 ? djlo : (djhi < 0 ? -djhi : 0);
        int dilo = ib - 256, dihi = ib + 63 - 256;
        int dim_ = dilo > 0 ? dilo : (dihi < 0 ? -dihi : 0);
        if (djm * djm + dim_ * dim_ > 65536) return;
    }

    const int Ah = (A + 1) / 2;
    const int aStart = h * Ah;
    const int aEnd   = min(A, aStart + Ah);

    for (int a = tid + aStart; a < aEnd; a += BPT) strig[a] = g_trig[a];

    const int dj = j - LDIM / 2;
    const float djf = (float)dj;
    float accA[4], accB[4], fdi[4];
    unsigned maskbits = 0;
    #pragma unroll
    for (int k = 0; k < 4; k++) {
        accA[k] = 0.f; accB[k] = 0.f;
        int di = i0 + 16 * k - LDIM / 2;
        bool outside = (di * di + dj * dj) > (LDIM / 2) * (LDIM / 2);
        if (outside) maskbits |= (1u << k);
        fdi[k] = (circle && outside) ? 0.0f : (float)di;
    }
    ull fdi2[2];
    #pragma unroll
    for (int q = 0; q < 2; q++) fdi2[q] = pack2(fdi[2 * q], fdi[2 * q + 1]);
    const ull mh2   = pack2(MAGIC - 0.5f, MAGIC - 0.5f);   // 8388607.5, representable
    const ull negM2 = pack2(-MAGIC, -MAGIC);
    const ull neg12 = pack2(-1.0f, -1.0f);

    const uint32_t sb = smem_u32(sm);
    const __half2* src = g_pairsh[b * A];
    const int nch = (aEnd - aStart + CH - 1) / CH;

    auto stage = [&](int cidx) {
        int a0 = aStart + cidx * CH;
        int ch = min(CH, aEnd - a0);
        uint32_t base = sb + (uint32_t)(cidx & 1) * BUFB;
        for (int r = 0; r < ch; r++) {
            const char* gsrc = (const char*)(src + (size_t)(a0 + r) * RP);
            uint32_t dst = base + (uint32_t)r * ROWB;
            for (int c = tid; c < ROWB / 16; c += BPT)
                cpa16(dst + (uint32_t)c * 16, gsrc + c * 16);
        }
        cpa_commit();
    };

    stage(0);

    for (int cidx = 0; cidx < nch; cidx++) {
        int a0 = aStart + cidx * CH;
        int ch = min(CH, aEnd - a0);

        cpa_wait0();             // this thread's groups (incl. chunk cidx) complete
        __syncthreads();         // all threads' data visible; all done computing cidx-1
        if (cidx + 1 < nch) stage(cidx + 1);   // buffer (cidx+1)&1 provably free

        uint32_t bb = sb + (uint32_t)(cidx & 1) * BUFB;
        if (circle) {
            #pragma unroll 2
            for (int r = 0; r < ch; r++) {
                float2 cs = strig[a0 + r];
                float base = fmaf(djf, cs.y, 256.5f);          // u' = t + 256.5 in [0.5,512.5]
                ull csx2  = pack2(cs.x, cs.x);
                ull base2 = pack2(base, base);
                // addr = bits(m)*4 + off, bits = 0x4B000000 + p  ->  bb + r*ROWB + 4*p
                uint32_t off = bb + (uint32_t)r * ROWB - 0x2C000000u;
                #pragma unroll
                for (int q = 0; q < 2; q++) {
                    ull u2  = fma2(fdi2[q], csx2, base2);
                    ull m2  = add2(u2, mh2);                   // bits = 0x4B000000 + floor(u')
                    ull fl2 = add2(m2, negM2);
                    ull f2  = fma2(fl2, neg12, u2);            // f = u' - floor(u')
                    uint32_t ad0 = (uint32_t)m2 * 4u + off;
                    uint32_t ad1 = (uint32_t)(m2 >> 32) * 4u + off;
                    float2 g0 = h2f2(lds32(ad0));
                    float2 g1 = h2f2(lds32(ad1));
                    accA[2 * q]     += g0.x;
                    accB[2 * q]      = fmaf(lo2(f2), g0.y, accB[2 * q]);
                    accA[2 * q + 1] += g1.x;
                    accB[2 * q + 1]  = fmaf(hi2(f2), g1.y, accB[2 * q + 1]);
                }
            }
        } else {
            for (int r = 0; r < ch; r++) {
                float2 cs = strig[a0 + r];
                float base = fmaf(djf, cs.y, 256.5f);          // u' in pair coords
                uint32_t rowa = bb + (uint32_t)r * ROWB;
                #pragma unroll
                for (int k = 0; k < 4; k++) {
                    float u = fmaf(fdi[k], cs.x, base);
                    int p = __float2int_rd(u);
                    float f = u - __int2float_rn(p);
                    int pc = min(max(p, 0), 512);
                    float2 g = h2f2(lds32(rowa + (uint32_t)pc * 4u));
                    float y0 = g.x;
                    float y1 = g.x + g.y;
                    float w0 = (p >= 1 && p <= 512) ? (1.0f - f) : 0.0f;
                    float w1 = (p >= 0 && p <= 511) ? f : 0.0f;
                    accA[k] = fmaf(w0, y0, fmaf(w1, y1, accA[k]));
                }
            }
        }
    }

    #pragma unroll
    for (int k = 0; k < 4; k++) {
        int ii = i0 + 16 * k;
        if (circle && ((maskbits >> k) & 1u)) continue;     // out pre-zeroed
        atomicAdd(&out[((size_t)b * LDIM + ii) * LDIM + j], accA[k] + accB[k]);
    }
}

// ---------------- launch ----------------
extern "C" void kernel_launch(void* const* d_in, const int* in_sizes, int n_in,
                              void* d_out, int out_size) {
    int si = 0, ai = 1, ci = 2;
    for (int i = 0; i < n_in; i++)
        if (in_sizes[i] > in_sizes[si]) si = i;
    for (int i = 0; i < n_in; i++) {
        if (i == si) continue;
        if (in_sizes[i] == 1) ci = i; else ai = i;
    }
    const float* sino   = (const float*)d_in[si];
    const float* angles = (const float*)d_in[ai];
    const int*   circ   = (const int*)d_in[ci];

    int A = in_sizes[ai];
    if (A > ADIM) A = ADIM;
    int BL = in_sizes[si] / A;
    int B  = BL / LDIM;
    if (B < 1) B = 1;
    if (B > BDIM) B = BDIM;
    int nrows = B * A;

    k_ramp<<<PDIM, 128>>>(angles, A, (float4*)d_out, out_size / 4);
    k_hr<<<PDIM, 256>>>();
    k_filter<<<nrows, 128>>>(sino);

    size_t smem = (size_t)(2 * BUFB) + (size_t)ADIM * sizeof(float2) + 16;
    cudaFuncSetAttribute(k_bp, cudaFuncAttributeMaxDynamicSharedMemorySize, (int)smem);
    dim3 grid(LDIM / 32, LDIM / 64, B * 2);   // z = (batch, angle-half)
    dim3 blk(32, 16);
    k_bp<<<grid, blk, smem>>>((float*)d_out, circ, A, B);
}

// round 16
// speedup vs baseline: 1.2771x; 1.1591x over previous
#include <cuda_runtime.h>
#include <stdint.h>

#define PI_F 3.14159265358979323846f

#define LDIM 512
#define ADIM 181
#define PDIM 1024
#define BDIM 2

#define RP    516                 // pairs per row (float2): p in [0,512] used, padded to 516
#define ROWB  (RP * 8)            // row bytes = 4128 (divisible by 16)
#define CH    13                  // angle rows per staging buffer (double-buffered)
#define BUFB  (CH * ROWB)         // 53664 bytes per buffer (multiple of 16)
#define MAGIC 8388608.0f          // 2^23 ; MAGIC-0.5f = 8388607.5 IS representable (ulp 0.5)

#define BPT   512                 // k_bp threads per block (32 x 16)

typedef unsigned long long ull;

// ---------------- device scratch (no allocation allowed) ----------------
__device__ float  g_F[PDIM];                    // frequency filter (ramp * shifted hann)
__device__ float  g_hr[PDIM];                   // real(ifft(F))  -- time-domain taps
__device__ float2 g_trig[ADIM];                 // (cos th, sin th), th = angle + pi/2
__device__ __align__(16) float2 g_pairs[BDIM * ADIM][RP]; // pair[p]=(c_p,d_p): val=c_p+u'*d_p

// ---------------- asm helpers ----------------
__device__ __forceinline__ uint32_t smem_u32(const void* p) {
    uint32_t a;
    asm("{ .reg .u64 t; cvta.to.shared.u64 t, %1; cvt.u32.u64 %0, t; }" : "=r"(a) : "l"(p));
    return a;
}
__device__ __forceinline__ void mbar_init(uint32_t mbar, uint32_t count) {
    asm volatile("mbarrier.init.shared.b64 [%0], %1;" :: "r"(mbar), "r"(count) : "memory");
}
__device__ __forceinline__ void mbar_expect_tx(uint32_t mbar, uint32_t bytes) {
    asm volatile("mbarrier.arrive.expect_tx.shared.b64 _, [%0], %1;"
                 :: "r"(mbar), "r"(bytes) : "memory");
}
__device__ __forceinline__ void bulk_g2s(uint32_t dst, const void* src,
                                         uint32_t bytes, uint32_t mbar) {
    asm volatile(
        "cp.async.bulk.shared::cluster.global.mbarrier::complete_tx::bytes "
        "[%0], [%1], %2, [%3];"
        :: "r"(dst), "l"(src), "r"(bytes), "r"(mbar) : "memory");
}
__device__ __forceinline__ void mbar_wait(uint32_t mbar, uint32_t parity) {
    asm volatile(
        "{\n\t"
        ".reg .pred P;\n\t"
        "WAIT_%=:\n\t"
        "mbarrier.try_wait.parity.acquire.cta.shared::cta.b64 P, [%0], %1, 0x989680;\n\t"
        "@P bra.uni DONE_%=;\n\t"
        "bra.uni WAIT_%=;\n\t"
        "DONE_%=:\n\t"
        "}"
        :: "r"(mbar), "r"(parity) : "memory");
}
__device__ __forceinline__ float2 lds64(uint32_t addr) {
    float2 g;
    asm volatile("ld.shared.v2.f32 {%0,%1}, [%2];" : "=f"(g.x), "=f"(g.y) : "r"(addr));
    return g;
}
__device__ __forceinline__ ull pack2(float lo, float hi) {
    ull d;
    asm("mov.b64 %0, {%1, %2};" : "=l"(d) : "f"(lo), "f"(hi));
    return d;
}
__device__ __forceinline__ ull fma2(ull a, ull b, ull c) {
    ull d;
    asm("fma.rn.f32x2 %0, %1, %2, %3;" : "=l"(d) : "l"(a), "l"(b), "l"(c));
    return d;
}
__device__ __forceinline__ ull add2(ull a, ull b) {
    ull d;
    asm("add.rn.f32x2 %0, %1, %2;" : "=l"(d) : "l"(a), "l"(b));
    return d;
}
__device__ __forceinline__ float lo2(ull d) { return __uint_as_float((unsigned)d); }
__device__ __forceinline__ float hi2(ull d) { return __uint_as_float((unsigned)(d >> 32)); }

// ---------------- F[k] = ramp[k] * fftshift(hanning(P))[k]  (+ trig, + zero d_out) ----------------
__global__ void k_ramp(const float* __restrict__ angles, int A,
                       float4* __restrict__ outz, int out_n4) {
    __shared__ float sred[4];
    int k = blockIdx.x;
    int t = threadIdx.x; // 128 threads

    // zero the output (replaces cudaMemsetAsync): 1024 blocks x 128 threads x 1 float4
    int zi = k * 128 + t;
    if (zi < out_n4) outz[zi] = make_float4(0.f, 0.f, 0.f, 0.f);

    float sum = 0.f;
    for (int j = t; j < 256; j += 128) {
        int m = 2 * j + 1;
        float fm = -1.0f / (PI_F * PI_F * (float)m * (float)m);
        int ph = (k * m) & (PDIM - 1);
        sum = fmaf(fm, cospif((float)ph * (1.0f / 512.0f)), sum);
    }
    #pragma unroll
    for (int o = 16; o; o >>= 1) sum += __shfl_down_sync(0xffffffffu, sum, o);
    if ((t & 31) == 0) sred[t >> 5] = sum;
    __syncthreads();
    if (t == 0) {
        float total = sred[0] + sred[1] + sred[2] + sred[3];
        float ramp = 0.5f + 4.0f * total;
        int i = (k + PDIM / 2) & (PDIM - 1);                       // fftshift index
        float w = 0.5f - 0.5f * cospif(2.0f * (float)i / 1023.0f); // np.hanning(1024)
        g_F[k] = ramp * w;
    }
    if (blockIdx.x == 0) {
        for (int a = t; a < A && a < ADIM; a += 128) {
            float th = angles[a] + PI_F * 0.5f;
            float s, c;
            sincosf(th, &s, &c);
            g_trig[a] = make_float2(c, s);
        }
    }
}

// ---------------- hr[n] = (1/P) * sum_k F[k] cos(2*pi*k*n/P) ----------------
__global__ void k_hr(void) {
    __shared__ float sred[8];
    int n = blockIdx.x;
    int t = threadIdx.x; // 256 threads
    float sum = 0.f;
    for (int k = t; k < PDIM; k += 256) {
        int ph = (k * n) & (PDIM - 1);
        sum = fmaf(g_F[k], cospif((float)ph * (1.0f / 512.0f)), sum);
    }
    #pragma unroll
    for (int o = 16; o; o >>= 1) sum += __shfl_down_sync(0xffffffffu, sum, o);
    if ((t & 31) == 0) sred[t >> 5] = sum;
    __syncthreads();
    if (t == 0) {
        float total = 0.f;
        #pragma unroll
        for (int w = 0; w < 8; w++) total += sred[w];
        g_hr[n] = total * (1.0f / (float)PDIM);
    }
}

// ---------------- filtering + affine-pair construction ----------------
// y[n] = sum_m x[m] hr[(n-m) mod 1024];  pair[p] = (c_p, d_p):
//   d_p = y[p]-y[p-1],  c_p = y[p-1] - p*d_p,  y[-1]=y[512]=0.
// In pair coords u' = t + 256.5 (cell p = floor(u')), interp value = c_p + u' * d_p.
__global__ void __launch_bounds__(128) k_filter(const float* __restrict__ sino) {
    __shared__ float xs[LDIM];
    __shared__ float hsx[1536];
    __shared__ float ysb[520];   // ysb[i] = y[i-1]; ysb[0]=0
    int row = blockIdx.x;
    int t = threadIdx.x; // 128
    const float4* x4 = (const float4*)(sino + row * LDIM);
    ((float4*)xs)[t] = x4[t];
    #pragma unroll
    for (int q = t; q < 384; q += 128)
        ((float4*)hsx)[q] = ((const float4*)g_hr)[q & 255];
    if (t == 0) ysb[0] = 0.f;
    __syncthreads();

    const int qb = 1024 + 4 * t;
    float4 Av = *(const float4*)(hsx + qb - 4);
    float4 Bv = *(const float4*)(hsx + qb);
    float acc0 = 0.f, acc1 = 0.f, acc2 = 0.f, acc3 = 0.f;

    #pragma unroll 4
    for (int m0 = 0; m0 < LDIM; m0 += 4) {
        float4 xv = *(const float4*)(xs + m0);
        float w0 = Av.x, w1 = Av.y, w2 = Av.z, w3 = Av.w;
        float w4 = Bv.x, w5 = Bv.y, w6 = Bv.z, w7 = Bv.w;
        acc0 = fmaf(xv.x, w4, fmaf(xv.y, w3, fmaf(xv.z, w2, fmaf(xv.w, w1, acc0))));
        acc1 = fmaf(xv.x, w5, fmaf(xv.y, w4, fmaf(xv.z, w3, fmaf(xv.w, w2, acc1))));
        acc2 = fmaf(xv.x, w6, fmaf(xv.y, w5, fmaf(xv.z, w4, fmaf(xv.w, w3, acc2))));
        acc3 = fmaf(xv.x, w7, fmaf(xv.y, w6, fmaf(xv.z, w5, fmaf(xv.w, w4, acc3))));
        Bv = Av;
        Av = *(const float4*)(hsx + qb - m0 - 8);
    }
    // y[4t..4t+3] -> ysb[4t+1 .. 4t+4]
    ysb[4 * t + 1] = acc0;
    ysb[4 * t + 2] = acc1;
    ysb[4 * t + 3] = acc2;
    ysb[4 * t + 4] = acc3;
    __syncthreads();

    float e0 = ysb[4 * t];       // y[4t-1]
    float pf = (float)(4 * t);   // pair index p for first of the 4
    float d0 = acc0 - e0;    float c0 = fmaf(-pf,          d0, e0);
    float d1 = acc1 - acc0;  float c1 = fmaf(-(pf + 1.0f), d1, acc0);
    float d2 = acc2 - acc1;  float c2 = fmaf(-(pf + 2.0f), d2, acc1);
    float d3 = acc3 - acc2;  float c3 = fmaf(-(pf + 3.0f), d3, acc2);
    float4* prow = (float4*)(&g_pairs[row][0]);
    prow[2 * t]     = make_float4(c0, d0, c1, d1);
    prow[2 * t + 1] = make_float4(c2, d2, c3, d3);
    if (t == 127)    // pair 512: d = -y[511], c = y[511] - 512*(-y[511]) = 513*y[511]
        g_pairs[row][512] = make_float2(513.0f * acc3, -acc3);
}

// ---------------- backprojection (TMA-bulk staging, angle-split, single-sync) ----------------
// block = (32,16) = 512 threads, 2 blocks/SM; tile = 32 (j) x 64 (i, 4 per thread).
// blockIdx.z = (batch, angle-half). Each chunk's CH contiguous pair-rows are fetched
// with ONE cp.async.bulk into the double buffer, completion via mbarrier expect_tx
// (buffer c&1, parity (c>>1)&1). One __syncthreads per chunk certifies both data
// visibility (all threads passed mbar_wait) and buffer-free for staging c+1.
// Hot loop arithmetic identical to the 55.8us R13 kernel.
__global__ void __launch_bounds__(BPT, 2) k_bp(
    float* __restrict__ out, const int* __restrict__ circ, int A, int B)
{
    extern __shared__ float sm[];
    float2* strig = (float2*)(sm + 2 * (BUFB / 4));
    // mbarriers after trig: offset in floats = 2*BUFB/4 + 2*ADIM -> 8-byte aligned
    uint32_t mb_off = (uint32_t)(2 * (BUFB / 4) + 2 * ADIM) * 4u;

    const int tx = threadIdx.x, ty = threadIdx.y;
    const int tid = ty * 32 + tx;
    const int b  = blockIdx.z >> 1;
    const int h  = blockIdx.z & 1;
    const int j  = blockIdx.x * 32 + tx;
    const int i0 = blockIdx.y * 64 + ty;
    const int circle = circ[0];

    // whole-block early exit: tile entirely outside the circle (output pre-zeroed)
    if (circle) {
        int j0 = (int)blockIdx.x * 32, ib = (int)blockIdx.y * 64;
        int djlo = j0 - 256, djhi = j0 + 31 - 256;
        int djm = djlo > 0 ? djlo : (djhi < 0 ? -djhi : 0);
        int dilo = ib - 256, dihi = ib + 63 - 256;
        int dim_ = dilo > 0 ? dilo : (dihi < 0 ? -dihi : 0);
        if (djm * djm + dim_ * dim_ > 65536) return;
    }

    const int Ah = (A + 1) / 2;
    const int aStart = h * Ah;
    const int aEnd   = min(A, aStart + Ah);

    const uint32_t sb = smem_u32(sm);
    const uint32_t mbar0 = sb + mb_off;
    const uint32_t mbar1 = mbar0 + 8;

    if (tid == 0) {
        mbar_init(mbar0, 1);
        mbar_init(mbar1, 1);
    }
    for (int a = tid + aStart; a < aEnd; a += BPT) strig[a] = g_trig[a];

    const int dj = j - LDIM / 2;
    const float djf = (float)dj;
    float accA[4], accB[4], fdi[4];
    unsigned maskbits = 0;
    #pragma unroll
    for (int k = 0; k < 4; k++) {
        accA[k] = 0.f; accB[k] = 0.f;
        int di = i0 + 16 * k - LDIM / 2;
        bool outside = (di * di + dj * dj) > (LDIM / 2) * (LDIM / 2);
        if (outside) maskbits |= (1u << k);
        fdi[k] = (circle && outside) ? 0.0f : (float)di;
    }
    ull fdi2[2];
    #pragma unroll
    for (int q = 0; q < 2; q++) fdi2[q] = pack2(fdi[2 * q], fdi[2 * q + 1]);
    const ull mh2 = pack2(MAGIC - 0.5f, MAGIC - 0.5f);   // 8388607.5, representable

    const float2* src = g_pairs[b * A];
    const int nA = aEnd - aStart;
    const int nch = (nA + CH - 1) / CH;

    __syncthreads();   // mbarrier init visible before first bulk

    // stage chunk 0: single bulk copy of ch*ROWB contiguous bytes
    if (tid == 0) {
        int ch0 = min(CH, nA);
        uint32_t bytes = (uint32_t)ch0 * ROWB;
        mbar_expect_tx(mbar0, bytes);
        bulk_g2s(sb, src + (size_t)aStart * RP, bytes, mbar0);
    }

    for (int cidx = 0; cidx < nch; cidx++) {
        int a0 = aStart + cidx * CH;
        int ch = min(CH, aEnd - a0);
        uint32_t mb = (cidx & 1) ? mbar1 : mbar0;
        uint32_t parity = (uint32_t)((cidx >> 1) & 1);

        mbar_wait(mb, parity);   // chunk cidx data resident in buf cidx&1
        __syncthreads();         // all threads saw it; all done computing cidx-1

        if (cidx + 1 < nch && tid == 0) {
            int a1 = a0 + CH;
            int ch1 = min(CH, aEnd - a1);
            uint32_t bytes = (uint32_t)ch1 * ROWB;
            uint32_t mbn = ((cidx + 1) & 1) ? mbar1 : mbar0;
            mbar_expect_tx(mbn, bytes);
            bulk_g2s(sb + (uint32_t)((cidx + 1) & 1) * BUFB,
                     src + (size_t)a1 * RP, bytes, mbn);
        }

        uint32_t bb = sb + (uint32_t)(cidx & 1) * BUFB;
        if (circle) {
            #pragma unroll 2
            for (int r = 0; r < ch; r++) {
                float2 cs = strig[a0 + r];
                float base = fmaf(djf, cs.y, 256.5f);          // u' = t + 256.5 in [0.5,512.5]
                ull csx2  = pack2(cs.x, cs.x);
                ull base2 = pack2(base, base);
                // addr = bits(m)*8 + off, bits = 0x4B000000 + p  ->  bb + r*ROWB + 8*p
                uint32_t off = bb + (uint32_t)r * ROWB - 0x58000000u;
                #pragma unroll
                for (int q = 0; q < 2; q++) {
                    ull u2 = fma2(fdi2[q], csx2, base2);
                    ull m2 = add2(u2, mh2);                    // bits = 0x4B000000 + floor(u')
                    uint32_t ad0 = (uint32_t)m2 * 8u + off;
                    uint32_t ad1 = (uint32_t)(m2 >> 32) * 8u + off;
                    float2 g0 = lds64(ad0);
                    float2 g1 = lds64(ad1);
                    accA[2 * q]     += g0.x;
                    accB[2 * q]      = fmaf(lo2(u2), g0.y, accB[2 * q]);
                    accA[2 * q + 1] += g1.x;
                    accB[2 * q + 1]  = fmaf(hi2(u2), g1.y, accB[2 * q + 1]);
                }
            }
        } else {
            for (int r = 0; r < ch; r++) {
                float2 cs = strig[a0 + r];
                float base = fmaf(djf, cs.y, 256.5f);          // u' in pair coords
                uint32_t rowa = bb + (uint32_t)r * ROWB;
                #pragma unroll
                for (int k = 0; k < 4; k++) {
                    float u = fmaf(fdi[k], cs.x, base);
                    int p = __float2int_rd(u);
                    float f = u - __int2float_rn(p);
                    int pc = min(max(p, 0), 512);
                    float2 g = lds64(rowa + (uint32_t)pc * 8u);
                    // endpoints of cell pc from affine coeffs: y0 = c + p*d, y1 = y0 + d
                    float y0 = fmaf((float)pc, g.y, g.x);
                    float y1 = y0 + g.y;
                    float w0 = (p >= 1 && p <= 512) ? (1.0f - f) : 0.0f;
                    float w1 = (p >= 0 && p <= 511) ? f : 0.0f;
                    accA[k] = fmaf(w0, y0, fmaf(w1, y1, accA[k]));
                }
            }
        }
    }

    #pragma unroll
    for (int k = 0; k < 4; k++) {
        int ii = i0 + 16 * k;
        if (circle && ((maskbits >> k) & 1u)) continue;     // out pre-zeroed
        atomicAdd(&out[((size_t)b * LDIM + ii) * LDIM + j], accA[k] + accB[k]);
    }
}

// ---------------- launch ----------------
extern "C" void kernel_launch(void* const* d_in, const int* in_sizes, int n_in,
                              void* d_out, int out_size) {
    int si = 0, ai = 1, ci = 2;
    for (int i = 0; i < n_in; i++)
        if (in_sizes[i] > in_sizes[si]) si = i;
    for (int i = 0; i < n_in; i++) {
        if (i == si) continue;
        if (in_sizes[i] == 1) ci = i; else ai = i;
    }
    const float* sino   = (const float*)d_in[si];
    const float* angles = (const float*)d_in[ai];
    const int*   circ   = (const int*)d_in[ci];

    int A = in_sizes[ai];
    if (A > ADIM) A = ADIM;
    int BL = in_sizes[si] / A;
    int B  = BL / LDIM;
    if (B < 1) B = 1;
    if (B > BDIM) B = BDIM;
    int nrows = B * A;

    k_ramp<<<PDIM, 128>>>(angles, A, (float4*)d_out, out_size / 4);
    k_hr<<<PDIM, 256>>>();
    k_filter<<<nrows, 128>>>(sino);

    size_t smem = (size_t)(2 * BUFB) + (size_t)(2 * ADIM) * sizeof(float) + 32;
    cudaFuncSetAttribute(k_bp, cudaFuncAttributeMaxDynamicSharedMemorySize, (int)smem);
    dim3 grid(LDIM / 32, LDIM / 64, B * 2);   // z = (batch, angle-half)
    dim3 blk(32, 16);
    k_bp<<<grid, blk, smem>>>((float*)d_out, circ, A, B);
}

// round 17
// speedup vs baseline: 1.3380x; 1.0477x over previous
#include <cuda_runtime.h>
#include <stdint.h>

#define PI_F 3.14159265358979323846f

#define LDIM 512
#define ADIM 181
#define PDIM 1024
#define BDIM 2

#define RP    516                 // pairs per row (float2): p in [0,512] used, padded to 516
#define ROWB  (RP * 8)            // row bytes = 4128 (divisible by 16)
#define CH    13                  // angle rows per staging buffer (double-buffered)
#define BUFB  (CH * ROWB)         // 53664 bytes per buffer (multiple of 16)
#define MAGIC 8388608.0f          // 2^23 ; MAGIC-0.5f = 8388607.5 IS representable (ulp 0.5)

#define BPT   512                 // k_bp threads per block (32 x 16)

typedef unsigned long long ull;

// ---------------- device scratch (no allocation allowed) ----------------
__device__ float  g_F[PDIM];                    // frequency filter (ramp * shifted hann)
__device__ float  g_hr[PDIM];                   // real(ifft(F))  -- time-domain taps
__device__ float2 g_trig[ADIM];                 // (cos th, sin th), th = angle + pi/2
__device__ __align__(16) float2 g_pairs[BDIM * ADIM][RP]; // pair[p]=(c_p,d_p): val=c_p+u'*d_p

// ---------------- asm helpers ----------------
__device__ __forceinline__ uint32_t smem_u32(const void* p) {
    uint32_t a;
    asm("{ .reg .u64 t; cvta.to.shared.u64 t, %1; cvt.u32.u64 %0, t; }" : "=r"(a) : "l"(p));
    return a;
}
__device__ __forceinline__ void mbar_init(uint32_t mbar, uint32_t count) {
    asm volatile("mbarrier.init.shared.b64 [%0], %1;" :: "r"(mbar), "r"(count) : "memory");
}
__device__ __forceinline__ void mbar_expect_tx(uint32_t mbar, uint32_t bytes) {
    asm volatile("mbarrier.arrive.expect_tx.shared.b64 _, [%0], %1;"
                 :: "r"(mbar), "r"(bytes) : "memory");
}
__device__ __forceinline__ void bulk_g2s(uint32_t dst, const void* src,
                                         uint32_t bytes, uint32_t mbar) {
    asm volatile(
        "cp.async.bulk.shared::cluster.global.mbarrier::complete_tx::bytes "
        "[%0], [%1], %2, [%3];"
        :: "r"(dst), "l"(src), "r"(bytes), "r"(mbar) : "memory");
}
__device__ __forceinline__ void mbar_wait(uint32_t mbar, uint32_t parity) {
    asm volatile(
        "{\n\t"
        ".reg .pred P;\n\t"
        "WAIT_%=:\n\t"
        "mbarrier.try_wait.parity.acquire.cta.shared::cta.b64 P, [%0], %1, 0x989680;\n\t"
        "@P bra.uni DONE_%=;\n\t"
        "bra.uni WAIT_%=;\n\t"
        "DONE_%=:\n\t"
        "}"
        :: "r"(mbar), "r"(parity) : "memory");
}
__device__ __forceinline__ float2 lds64(uint32_t addr) {
    float2 g;
    asm volatile("ld.shared.v2.f32 {%0,%1}, [%2];" : "=f"(g.x), "=f"(g.y) : "r"(addr));
    return g;
}
__device__ __forceinline__ ull pack2(float lo, float hi) {
    ull d;
    asm("mov.b64 %0, {%1, %2};" : "=l"(d) : "f"(lo), "f"(hi));
    return d;
}
__device__ __forceinline__ ull fma2(ull a, ull b, ull c) {
    ull d;
    asm("fma.rn.f32x2 %0, %1, %2, %3;" : "=l"(d) : "l"(a), "l"(b), "l"(c));
    return d;
}
__device__ __forceinline__ ull add2(ull a, ull b) {
    ull d;
    asm("add.rn.f32x2 %0, %1, %2;" : "=l"(d) : "l"(a), "l"(b));
    return d;
}
__device__ __forceinline__ float lo2(ull d) { return __uint_as_float((unsigned)d); }
__device__ __forceinline__ float hi2(ull d) { return __uint_as_float((unsigned)(d >> 32)); }

// ---------------- F[k] = ramp[k] * fftshift(hanning(P))[k]  (+ trig, + zero d_out) ----------------
__global__ void k_ramp(const float* __restrict__ angles, int A,
                       float4* __restrict__ outz, int out_n4) {
    __shared__ float sred[4];
    int k = blockIdx.x;
    int t = threadIdx.x; // 128 threads

    // zero the output (replaces cudaMemsetAsync): 1024 blocks x 128 threads x 1 float4
    int zi = k * 128 + t;
    if (zi < out_n4) outz[zi] = make_float4(0.f, 0.f, 0.f, 0.f);

    float sum = 0.f;
    for (int j = t; j < 256; j += 128) {
        int m = 2 * j + 1;
        float fm = -1.0f / (PI_F * PI_F * (float)m * (float)m);
        int ph = (k * m) & (PDIM - 1);
        sum = fmaf(fm, cospif((float)ph * (1.0f / 512.0f)), sum);
    }
    #pragma unroll
    for (int o = 16; o; o >>= 1) sum += __shfl_down_sync(0xffffffffu, sum, o);
    if ((t & 31) == 0) sred[t >> 5] = sum;
    __syncthreads();
    if (t == 0) {
        float total = sred[0] + sred[1] + sred[2] + sred[3];
        float ramp = 0.5f + 4.0f * total;
        int i = (k + PDIM / 2) & (PDIM - 1);                       // fftshift index
        float w = 0.5f - 0.5f * cospif(2.0f * (float)i / 1023.0f); // np.hanning(1024)
        g_F[k] = ramp * w;
    }
    if (blockIdx.x == 0) {
        for (int a = t; a < A && a < ADIM; a += 128) {
            float th = angles[a] + PI_F * 0.5f;
            float s, c;
            sincosf(th, &s, &c);
            g_trig[a] = make_float2(c, s);
        }
    }
}

// ---------------- hr[n] = (1/P) * sum_k F[k] cos(2*pi*k*n/P) ----------------
__global__ void k_hr(void) {
    __shared__ float sred[8];
    int n = blockIdx.x;
    int t = threadIdx.x; // 256 threads
    float sum = 0.f;
    for (int k = t; k < PDIM; k += 256) {
        int ph = (k * n) & (PDIM - 1);
        sum = fmaf(g_F[k], cospif((float)ph * (1.0f / 512.0f)), sum);
    }
    #pragma unroll
    for (int o = 16; o; o >>= 1) sum += __shfl_down_sync(0xffffffffu, sum, o);
    if ((t & 31) == 0) sred[t >> 5] = sum;
    __syncthreads();
    if (t == 0) {
        float total = 0.f;
        #pragma unroll
        for (int w = 0; w < 8; w++) total += sred[w];
        g_hr[n] = total * (1.0f / (float)PDIM);
    }
}

// ---------------- filtering + affine-pair construction ----------------
// y[n] = sum_m x[m] hr[(n-m) mod 1024];  pair[p] = (c_p, d_p):
//   d_p = y[p]-y[p-1],  c_p = y[p-1] - p*d_p,  y[-1]=y[512]=0.
// In pair coords u' = t + 256.5 (cell p = floor(u')), interp value = c_p + u' * d_p.
__global__ void __launch_bounds__(128) k_filter(const float* __restrict__ sino) {
    __shared__ float xs[LDIM];
    __shared__ float hsx[1536];
    __shared__ float ysb[520];   // ysb[i] = y[i-1]; ysb[0]=0
    int row = blockIdx.x;
    int t = threadIdx.x; // 128
    const float4* x4 = (const float4*)(sino + row * LDIM);
    ((float4*)xs)[t] = x4[t];
    #pragma unroll
    for (int q = t; q < 384; q += 128)
        ((float4*)hsx)[q] = ((const float4*)g_hr)[q & 255];
    if (t == 0) ysb[0] = 0.f;
    __syncthreads();

    const int qb = 1024 + 4 * t;
    float4 Av = *(const float4*)(hsx + qb - 4);
    float4 Bv = *(const float4*)(hsx + qb);
    float acc0 = 0.f, acc1 = 0.f, acc2 = 0.f, acc3 = 0.f;

    #pragma unroll 4
    for (int m0 = 0; m0 < LDIM; m0 += 4) {
        float4 xv = *(const float4*)(xs + m0);
        float w0 = Av.x, w1 = Av.y, w2 = Av.z, w3 = Av.w;
        float w4 = Bv.x, w5 = Bv.y, w6 = Bv.z, w7 = Bv.w;
        acc0 = fmaf(xv.x, w4, fmaf(xv.y, w3, fmaf(xv.z, w2, fmaf(xv.w, w1, acc0))));
        acc1 = fmaf(xv.x, w5, fmaf(xv.y, w4, fmaf(xv.z, w3, fmaf(xv.w, w2, acc1))));
        acc2 = fmaf(xv.x, w6, fmaf(xv.y, w5, fmaf(xv.z, w4, fmaf(xv.w, w3, acc2))));
        acc3 = fmaf(xv.x, w7, fmaf(xv.y, w6, fmaf(xv.z, w5, fmaf(xv.w, w4, acc3))));
        Bv = Av;
        Av = *(const float4*)(hsx + qb - m0 - 8);
    }
    // y[4t..4t+3] -> ysb[4t+1 .. 4t+4]
    ysb[4 * t + 1] = acc0;
    ysb[4 * t + 2] = acc1;
    ysb[4 * t + 3] = acc2;
    ysb[4 * t + 4] = acc3;
    __syncthreads();

    float e0 = ysb[4 * t];       // y[4t-1]
    float pf = (float)(4 * t);   // pair index p for first of the 4
    float d0 = acc0 - e0;    float c0 = fmaf(-pf,          d0, e0);
    float d1 = acc1 - acc0;  float c1 = fmaf(-(pf + 1.0f), d1, acc0);
    float d2 = acc2 - acc1;  float c2 = fmaf(-(pf + 2.0f), d2, acc1);
    float d3 = acc3 - acc2;  float c3 = fmaf(-(pf + 3.0f), d3, acc2);
    float4* prow = (float4*)(&g_pairs[row][0]);
    prow[2 * t]     = make_float4(c0, d0, c1, d1);
    prow[2 * t + 1] = make_float4(c2, d2, c3, d3);
    if (t == 127)    // pair 512: d = -y[511], c = y[511] - 512*(-y[511]) = 513*y[511]
        g_pairs[row][512] = make_float2(513.0f * acc3, -acc3);
}

// ---------------- backprojection (TMA staging, constant-trip unrolled chunks) ----------------
// block = (32,16) = 512 threads, 2 blocks/SM; tile = 32 (j) x 64 (i, 4 per thread).
// blockIdx.z = (batch, angle-half). One cp.async.bulk per chunk (mbarrier expect_tx,
// buffer c&1, parity (c>>1)&1); one __syncthreads per chunk. Full chunks (ch==CH)
// run a fully-unrolled 13-angle body: constant r folds addressing into immediates
// and removes loop machinery. Hot-loop arithmetic identical to the R16 winner.
__global__ void __launch_bounds__(BPT, 2) k_bp(
    float* __restrict__ out, const int* __restrict__ circ, int A, int B)
{
    extern __shared__ float sm[];
    float2* strig = (float2*)(sm + 2 * (BUFB / 4));
    uint32_t mb_off = (uint32_t)(2 * (BUFB / 4) + 2 * ADIM) * 4u;

    const int tx = threadIdx.x, ty = threadIdx.y;
    const int tid = ty * 32 + tx;
    const int b  = blockIdx.z >> 1;
    const int h  = blockIdx.z & 1;
    const int j  = blockIdx.x * 32 + tx;
    const int i0 = blockIdx.y * 64 + ty;
    const int circle = circ[0];

    // whole-block early exit: tile entirely outside the circle (output pre-zeroed)
    if (circle) {
        int j0 = (int)blockIdx.x * 32, ib = (int)blockIdx.y * 64;
        int djlo = j0 - 256, djhi = j0 + 31 - 256;
        int djm = djlo > 0 ? djlo : (djhi < 0 ? -djhi : 0);
        int dilo = ib - 256, dihi = ib + 63 - 256;
        int dim_ = dilo > 0 ? dilo : (dihi < 0 ? -dihi : 0);
        if (djm * djm + dim_ * dim_ > 65536) return;
    }

    const int Ah = (A + 1) / 2;
    const int aStart = h * Ah;
    const int aEnd   = min(A, aStart + Ah);

    const uint32_t sb = smem_u32(sm);
    const uint32_t mbar0 = sb + mb_off;
    const uint32_t mbar1 = mbar0 + 8;

    if (tid == 0) {
        mbar_init(mbar0, 1);
        mbar_init(mbar1, 1);
    }
    for (int a = tid + aStart; a < aEnd; a += BPT) strig[a] = g_trig[a];

    const int dj = j - LDIM / 2;
    const float djf = (float)dj;
    float accA[4], accB[4], fdi[4];
    unsigned maskbits = 0;
    #pragma unroll
    for (int k = 0; k < 4; k++) {
        accA[k] = 0.f; accB[k] = 0.f;
        int di = i0 + 16 * k - LDIM / 2;
        bool outside = (di * di + dj * dj) > (LDIM / 2) * (LDIM / 2);
        if (outside) maskbits |= (1u << k);
        fdi[k] = (circle && outside) ? 0.0f : (float)di;
    }
    ull fdi2[2];
    #pragma unroll
    for (int q = 0; q < 2; q++) fdi2[q] = pack2(fdi[2 * q], fdi[2 * q + 1]);
    const ull mh2 = pack2(MAGIC - 0.5f, MAGIC - 0.5f);   // 8388607.5, representable

    const float2* src = g_pairs[b * A];
    const int nA = aEnd - aStart;
    const int nch = (nA + CH - 1) / CH;

    __syncthreads();   // mbarrier init visible before first bulk

    if (tid == 0) {
        int ch0 = min(CH, nA);
        uint32_t bytes = (uint32_t)ch0 * ROWB;
        mbar_expect_tx(mbar0, bytes);
        bulk_g2s(sb, src + (size_t)aStart * RP, bytes, mbar0);
    }

    // one-angle sample body (r constant-propagated when called from unrolled loop)
    auto body = [&](uint32_t bb, int a0, int r) {
        float2 cs = strig[a0 + r];
        float base = fmaf(djf, cs.y, 256.5f);              // u' = t + 256.5 in [0.5,512.5]
        ull csx2  = pack2(cs.x, cs.x);
        ull base2 = pack2(base, base);
        uint32_t off = bb + (uint32_t)r * ROWB - 0x58000000u; // bits(m)*8+off = row + 8*p
        #pragma unroll
        for (int q = 0; q < 2; q++) {
            ull u2 = fma2(fdi2[q], csx2, base2);
            ull m2 = add2(u2, mh2);                        // bits = 0x4B000000 + floor(u')
            uint32_t ad0 = (uint32_t)m2 * 8u + off;
            uint32_t ad1 = (uint32_t)(m2 >> 32) * 8u + off;
            float2 g0 = lds64(ad0);
            float2 g1 = lds64(ad1);
            accA[2 * q]     += g0.x;
            accB[2 * q]      = fmaf(lo2(u2), g0.y, accB[2 * q]);
            accA[2 * q + 1] += g1.x;
            accB[2 * q + 1]  = fmaf(hi2(u2), g1.y, accB[2 * q + 1]);
        }
    };

    for (int cidx = 0; cidx < nch; cidx++) {
        int a0 = aStart + cidx * CH;
        int ch = min(CH, aEnd - a0);
        uint32_t mb = (cidx & 1) ? mbar1 : mbar0;
        uint32_t parity = (uint32_t)((cidx >> 1) & 1);

        mbar_wait(mb, parity);   // chunk cidx data resident in buf cidx&1
        __syncthreads();         // all threads saw it; all done computing cidx-1

        if (cidx + 1 < nch && tid == 0) {
            int a1 = a0 + CH;
            int ch1 = min(CH, aEnd - a1);
            uint32_t bytes = (uint32_t)ch1 * ROWB;
            uint32_t mbn = ((cidx + 1) & 1) ? mbar1 : mbar0;
            mbar_expect_tx(mbn, bytes);
            bulk_g2s(sb + (uint32_t)((cidx + 1) & 1) * BUFB,
                     src + (size_t)a1 * RP, bytes, mbn);
        }

        uint32_t bb = sb + (uint32_t)(cidx & 1) * BUFB;
        if (circle) {
            if (ch == CH) {
                #pragma unroll
                for (int r = 0; r < CH; r++) body(bb, a0, r);
            } else {
                for (int r = 0; r < ch; r++) body(bb, a0, r);
            }
        } else {
            for (int r = 0; r < ch; r++) {
                float2 cs = strig[a0 + r];
                float base = fmaf(djf, cs.y, 256.5f);          // u' in pair coords
                uint32_t rowa = bb + (uint32_t)r * ROWB;
                #pragma unroll
                for (int k = 0; k < 4; k++) {
                    float u = fmaf(fdi[k], cs.x, base);
                    int p = __float2int_rd(u);
                    float f = u - __int2float_rn(p);
                    int pc = min(max(p, 0), 512);
                    float2 g = lds64(rowa + (uint32_t)pc * 8u);
                    // endpoints of cell pc from affine coeffs: y0 = c + p*d, y1 = y0 + d
                    float y0 = fmaf((float)pc, g.y, g.x);
                    float y1 = y0 + g.y;
                    float w0 = (p >= 1 && p <= 512) ? (1.0f - f) : 0.0f;
                    float w1 = (p >= 0 && p <= 511) ? f : 0.0f;
                    accA[k] = fmaf(w0, y0, fmaf(w1, y1, accA[k]));
                }
            }
        }
    }

    #pragma unroll
    for (int k = 0; k < 4; k++) {
        int ii = i0 + 16 * k;
        if (circle && ((maskbits >> k) & 1u)) continue;     // out pre-zeroed
        atomicAdd(&out[((size_t)b * LDIM + ii) * LDIM + j], accA[k] + accB[k]);
    }
}

// ---------------- launch ----------------
extern "C" void kernel_launch(void* const* d_in, const int* in_sizes, int n_in,
                              void* d_out, int out_size) {
    int si = 0, ai = 1, ci = 2;
    for (int i = 0; i < n_in; i++)
        if (in_sizes[i] > in_sizes[si]) si = i;
    for (int i = 0; i < n_in; i++) {
        if (i == si) continue;
        if (in_sizes[i] == 1) ci = i; else ai = i;
    }
    const float* sino   = (const float*)d_in[si];
    const float* angles = (const float*)d_in[ai];
    const int*   circ   = (const int*)d_in[ci];

    int A = in_sizes[ai];
    if (A > ADIM) A = ADIM;
    int BL = in_sizes[si] / A;
    int B  = BL / LDIM;
    if (B < 1) B = 1;
    if (B > BDIM) B = BDIM;
    int nrows = B * A;

    k_ramp<<<PDIM, 128>>>(angles, A, (float4*)d_out, out_size / 4);
    k_hr<<<PDIM, 256>>>();
    k_filter<<<nrows, 128>>>(sino);

    size_t smem = (size_t)(2 * BUFB) + (size_t)(2 * ADIM) * sizeof(float) + 32;
    cudaFuncSetAttribute(k_bp, cudaFuncAttributeMaxDynamicSharedMemorySize, (int)smem);
    dim3 grid(LDIM / 32, LDIM / 64, B * 2);   // z = (batch, angle-half)
    dim3 blk(32, 16);
    k_bp<<<grid, blk, smem>>>((float*)d_out, circ, A, B);
}